// round 1
// baseline (speedup 1.0000x reference)
#include <cuda_runtime.h>
#include <math.h>

#define T_SEQ   4096
#define B_BATCH 4
#define C_EMB   1024
#define H_DIM   64
#define NROWS   (B_BATCH * T_SEQ)   // 16384

// Scratch for projected Q/K/V (no cudaMalloc allowed)
__device__ float g_Q[NROWS * H_DIM];
__device__ float g_K[NROWS * H_DIM];
__device__ float g_V[NROWS * H_DIM];

// ---------------------------------------------------------------------------
// Kernel 1: QKV projection.  C[16384,64] = X[16384,1024] @ W[1024,64], x3.
// Block: 256 threads -> 64-row x 64-col tile, k-chunks of 32.
// Thread (ty,tx) in 16x16 layout computes a 4x4 micro-tile.
// ---------------------------------------------------------------------------
__global__ __launch_bounds__(256) void proj_kernel(
    const float* __restrict__ x,
    const float* __restrict__ Wq,
    const float* __restrict__ Wk,
    const float* __restrict__ Wv)
{
    const float* W;
    float* outp;
    if (blockIdx.y == 0)      { W = Wq; outp = g_Q; }
    else if (blockIdx.y == 1) { W = Wk; outp = g_K; }
    else                      { W = Wv; outp = g_V; }

    __shared__ float Xs[64][36];   // 64 rows x 32 k (pad 36, 16B-aligned rows)
    __shared__ float Ws[32][68];   // 32 k x 64 cols (pad 68)

    const int tid = threadIdx.x;
    const int ty = tid >> 4;
    const int tx = tid & 15;
    const int row0 = blockIdx.x * 64;

    float acc[4][4];
#pragma unroll
    for (int i = 0; i < 4; i++)
#pragma unroll
        for (int j = 0; j < 4; j++) acc[i][j] = 0.0f;

    for (int k0 = 0; k0 < C_EMB; k0 += 32) {
        // fill Xs: 64 rows x 8 float4
        for (int i = tid; i < 512; i += 256) {
            int r = i >> 3, c4 = i & 7;
            float4 v = *(const float4*)(x + (size_t)(row0 + r) * C_EMB + k0 + c4 * 4);
            *(float4*)&Xs[r][c4 * 4] = v;
        }
        // fill Ws: 32 rows x 16 float4
        for (int i = tid; i < 512; i += 256) {
            int r = i >> 4, c4 = i & 15;
            float4 v = *(const float4*)(W + (size_t)(k0 + r) * H_DIM + c4 * 4);
            *(float4*)&Ws[r][c4 * 4] = v;
        }
        __syncthreads();

#pragma unroll 8
        for (int k = 0; k < 32; k++) {
            float xv[4];
#pragma unroll
            for (int i = 0; i < 4; i++) xv[i] = Xs[ty * 4 + i][k];
            float4 wv = *(const float4*)&Ws[k][tx * 4];
            float wr[4] = {wv.x, wv.y, wv.z, wv.w};
#pragma unroll
            for (int i = 0; i < 4; i++)
#pragma unroll
                for (int j = 0; j < 4; j++)
                    acc[i][j] = fmaf(xv[i], wr[j], acc[i][j]);
        }
        __syncthreads();
    }

#pragma unroll
    for (int i = 0; i < 4; i++)
#pragma unroll
        for (int j = 0; j < 4; j++)
            outp[(size_t)(row0 + ty * 4 + i) * H_DIM + tx * 4 + j] = acc[i][j];
}

// ---------------------------------------------------------------------------
// Kernel 2: causal flash attention.  BM=64 query rows per block, BN=32 keys
// per inner tile.  256 threads, (ty,tx) 16x16.
//  S micro-tile: 4 rows x 2 keys.  O micro-tile: 4 rows x 4 head dims.
//  K stored transposed in smem (conflict-free scalar reads).
//  P staged through smem between S and PV phases.
// ---------------------------------------------------------------------------
__global__ __launch_bounds__(256) void flash_kernel(float* __restrict__ out)
{
    const int b  = blockIdx.y;
    const int qb = (T_SEQ / 64 - 1) - blockIdx.x;   // heavy blocks first
    const int row0 = qb * 64;

    const float* Qp = g_Q + (size_t)b * T_SEQ * H_DIM;
    const float* Kp = g_K + (size_t)b * T_SEQ * H_DIM;
    const float* Vp = g_V + (size_t)b * T_SEQ * H_DIM;

    __shared__ float Qs[64][68];    // [row][k]
    __shared__ float Kst[64][33];   // transposed: [k][key-in-tile]
    __shared__ float Vs[32][68];    // [key-in-tile][h]
    __shared__ float Ps[64][34];    // [row][key-in-tile]

    const int tid = threadIdx.x;
    const int ty = tid >> 4;
    const int tx = tid & 15;

    // load Q tile (64 x 64): 1024 float4 ops
    for (int i = tid; i < 1024; i += 256) {
        int r = i >> 4, c4 = i & 15;
        *(float4*)&Qs[r][c4 * 4] =
            *(const float4*)(Qp + (size_t)(row0 + r) * H_DIM + c4 * 4);
    }

    float m_i[4], l_i[4], acc[4][4];
#pragma unroll
    for (int i = 0; i < 4; i++) {
        m_i[i] = -1e30f;
        l_i[i] = 0.0f;
#pragma unroll
        for (int j = 0; j < 4; j++) acc[i][j] = 0.0f;
    }

    const int nkb = (row0 + 64) / 32;   // key tiles 0 .. 2*qb+1
    for (int kb = 0; kb < nkb; kb++) {
        __syncthreads();   // previous PV / initial Q load complete

        // fill K transposed: 2048 scalars, coalesced global reads
        for (int i = tid; i < 2048; i += 256) {
            int c = i >> 6, k = i & 63;
            Kst[k][c] = Kp[(size_t)(kb * 32 + c) * H_DIM + k];
        }
        // fill V: 512 float4
        for (int i = tid; i < 512; i += 256) {
            int r = i >> 4, c4 = i & 15;
            *(float4*)&Vs[r][c4 * 4] =
                *(const float4*)(Vp + (size_t)(kb * 32 + r) * H_DIM + c4 * 4);
        }
        __syncthreads();

        // ---- S = Q K^T (rows ty*4.., keys tx*2..), dot over 64 ----
        float s[4][2];
#pragma unroll
        for (int i = 0; i < 4; i++) { s[i][0] = 0.0f; s[i][1] = 0.0f; }

#pragma unroll 4
        for (int k = 0; k < 64; k += 4) {
            float q_[4][4];
#pragma unroll
            for (int i = 0; i < 4; i++) {
                float4 t = *(const float4*)&Qs[ty * 4 + i][k];
                q_[i][0] = t.x; q_[i][1] = t.y; q_[i][2] = t.z; q_[i][3] = t.w;
            }
#pragma unroll
            for (int kk = 0; kk < 4; kk++) {
                float kv0 = Kst[k + kk][tx * 2];
                float kv1 = Kst[k + kk][tx * 2 + 1];
#pragma unroll
                for (int i = 0; i < 4; i++) {
                    s[i][0] = fmaf(q_[i][kk], kv0, s[i][0]);
                    s[i][1] = fmaf(q_[i][kk], kv1, s[i][1]);
                }
            }
        }

        // ---- scale + causal mask ----
        const bool need_mask = (kb * 32 + 31) > row0;
#pragma unroll
        for (int i = 0; i < 4; i++)
#pragma unroll
            for (int j = 0; j < 2; j++) {
                s[i][j] *= 0.125f;
                if (need_mask) {
                    int key  = kb * 32 + tx * 2 + j;
                    int rowg = row0 + ty * 4 + i;
                    if (key > rowg) s[i][j] = -1e30f;
                }
            }

        // ---- online softmax ----
        float tm[4];
#pragma unroll
        for (int i = 0; i < 4; i++) tm[i] = fmaxf(s[i][0], s[i][1]);
#pragma unroll
        for (int msk = 8; msk; msk >>= 1)
#pragma unroll
            for (int i = 0; i < 4; i++)
                tm[i] = fmaxf(tm[i], __shfl_xor_sync(0xffffffffu, tm[i], msk));

        float p[4][2], ts[4], alpha[4];
#pragma unroll
        for (int i = 0; i < 4; i++) {
            float mn = fmaxf(m_i[i], tm[i]);
            alpha[i] = __expf(m_i[i] - mn);
            m_i[i] = mn;
            p[i][0] = __expf(s[i][0] - mn);
            p[i][1] = __expf(s[i][1] - mn);
            ts[i] = p[i][0] + p[i][1];
        }
#pragma unroll
        for (int msk = 8; msk; msk >>= 1)
#pragma unroll
            for (int i = 0; i < 4; i++)
                ts[i] += __shfl_xor_sync(0xffffffffu, ts[i], msk);
#pragma unroll
        for (int i = 0; i < 4; i++) {
            l_i[i] = l_i[i] * alpha[i] + ts[i];
#pragma unroll
            for (int j = 0; j < 4; j++) acc[i][j] *= alpha[i];
        }

        // stage P (previous readers already synced at loop top)
#pragma unroll
        for (int i = 0; i < 4; i++) {
            Ps[ty * 4 + i][tx * 2]     = p[i][0];
            Ps[ty * 4 + i][tx * 2 + 1] = p[i][1];
        }
        __syncthreads();

        // ---- O += P V  (rows ty*4.., head dims tx*4..) ----
#pragma unroll 4
        for (int ks = 0; ks < 32; ks++) {
            float pv[4];
#pragma unroll
            for (int i = 0; i < 4; i++) pv[i] = Ps[ty * 4 + i][ks];
            float4 vv = *(const float4*)&Vs[ks][tx * 4];
            float vr[4] = {vv.x, vv.y, vv.z, vv.w};
#pragma unroll
            for (int i = 0; i < 4; i++)
#pragma unroll
                for (int j = 0; j < 4; j++)
                    acc[i][j] = fmaf(pv[i], vr[j], acc[i][j]);
        }
    }

    // ---- write normalized output ----
#pragma unroll
    for (int i = 0; i < 4; i++) {
        float inv = 1.0f / l_i[i];
#pragma unroll
        for (int j = 0; j < 4; j++)
            out[(size_t)b * T_SEQ * H_DIM +
                (size_t)(row0 + ty * 4 + i) * H_DIM + tx * 4 + j] = acc[i][j] * inv;
    }
}

// ---------------------------------------------------------------------------
extern "C" void kernel_launch(void* const* d_in, const int* in_sizes, int n_in,
                              void* d_out, int out_size)
{
    const float* x  = (const float*)d_in[0];
    const float* Wq = (const float*)d_in[1];
    const float* Wk = (const float*)d_in[2];
    const float* Wv = (const float*)d_in[3];
    float* out = (float*)d_out;

    dim3 g1(NROWS / 64, 3);
    proj_kernel<<<g1, 256>>>(x, Wq, Wk, Wv);

    dim3 g2(T_SEQ / 64, B_BATCH);
    flash_kernel<<<g2, 256>>>(out);
}

// round 2
// speedup vs baseline: 2.0572x; 2.0572x over previous
#include <cuda_runtime.h>
#include <math.h>

#define T_SEQ   4096
#define B_BATCH 4
#define C_EMB   1024
#define H_DIM   64
#define NROWS   (B_BATCH * T_SEQ)   // 16384

__device__ float g_Q[NROWS * H_DIM];
__device__ float g_K[NROWS * H_DIM];
__device__ float g_V[NROWS * H_DIM];

// ---- helpers -------------------------------------------------------------
__device__ __forceinline__ unsigned f2tf(float f) {
    unsigned r;
    asm("cvt.rna.tf32.f32 %0, %1;" : "=r"(r) : "f"(f));
    return r;
}
__device__ __forceinline__ float tfbits(float f) {
    return __uint_as_float(f2tf(f));
}
// D += A(16x8,row) * B(8x8,col-frag)   tf32 -> f32
__device__ __forceinline__ void mma_tf32(float* d, const unsigned* a, const unsigned* b) {
    asm("mma.sync.aligned.m16n8k8.row.col.f32.tf32.tf32.f32 "
        "{%0,%1,%2,%3}, {%4,%5,%6,%7}, {%8,%9}, {%0,%1,%2,%3};"
        : "+f"(d[0]), "+f"(d[1]), "+f"(d[2]), "+f"(d[3])
        : "r"(a[0]), "r"(a[1]), "r"(a[2]), "r"(a[3]), "r"(b[0]), "r"(b[1]));
}

// ---------------------------------------------------------------------------
// Kernel 1: QKV projection via tf32 mma.sync.
// Block 256 thr = 8 warps; tile 128 rows x 64 cols; k-chunks of 32.
// Warp w -> rows w*16..w*16+15, all 64 cols (8 n-atoms).
// ---------------------------------------------------------------------------
__global__ __launch_bounds__(256) void proj_kernel(
    const float* __restrict__ x,
    const float* __restrict__ Wq,
    const float* __restrict__ Wk,
    const float* __restrict__ Wv)
{
    const float* W;
    float* outp;
    if (blockIdx.y == 0)      { W = Wq; outp = g_Q; }
    else if (blockIdx.y == 1) { W = Wk; outp = g_K; }
    else                      { W = Wv; outp = g_V; }

    __shared__ float Xs[128][36];  // [row][k]  pitch 36 -> A-frag conflict-free
    __shared__ float Ws[32][72];   // [k][n]    pitch 72 -> B-frag conflict-free

    const int tid  = threadIdx.x;
    const int warp = tid >> 5;
    const int lane = tid & 31;
    const int g  = lane >> 2;      // groupID (row within atom)
    const int tg = lane & 3;       // thread-in-group (k / col pair)
    const int row0 = blockIdx.x * 128;

    float acc[8][4];
#pragma unroll
    for (int a = 0; a < 8; a++)
#pragma unroll
        for (int j = 0; j < 4; j++) acc[a][j] = 0.0f;

    for (int k0 = 0; k0 < C_EMB; k0 += 32) {
        // Xs: 128 rows x 8 float4
        for (int i = tid; i < 1024; i += 256) {
            int r = i >> 3, c4 = i & 7;
            float4 v = *(const float4*)(x + (size_t)(row0 + r) * C_EMB + k0 + c4 * 4);
            Xs[r][c4 * 4 + 0] = tfbits(v.x);
            Xs[r][c4 * 4 + 1] = tfbits(v.y);
            Xs[r][c4 * 4 + 2] = tfbits(v.z);
            Xs[r][c4 * 4 + 3] = tfbits(v.w);
        }
        // Ws: 32 rows x 16 float4
        for (int i = tid; i < 512; i += 256) {
            int r = i >> 4, c4 = i & 15;
            float4 v = *(const float4*)(W + (size_t)(k0 + r) * H_DIM + c4 * 4);
            Ws[r][c4 * 4 + 0] = tfbits(v.x);
            Ws[r][c4 * 4 + 1] = tfbits(v.y);
            Ws[r][c4 * 4 + 2] = tfbits(v.z);
            Ws[r][c4 * 4 + 3] = tfbits(v.w);
        }
        __syncthreads();

#pragma unroll
        for (int kc = 0; kc < 32; kc += 8) {
            unsigned a[4];
            a[0] = __float_as_uint(Xs[warp * 16 + g    ][kc + tg    ]);
            a[1] = __float_as_uint(Xs[warp * 16 + g + 8][kc + tg    ]);
            a[2] = __float_as_uint(Xs[warp * 16 + g    ][kc + tg + 4]);
            a[3] = __float_as_uint(Xs[warp * 16 + g + 8][kc + tg + 4]);
#pragma unroll
            for (int at = 0; at < 8; at++) {
                unsigned b[2];
                b[0] = __float_as_uint(Ws[kc + tg    ][at * 8 + g]);
                b[1] = __float_as_uint(Ws[kc + tg + 4][at * 8 + g]);
                mma_tf32(acc[at], a, b);
            }
        }
        __syncthreads();
    }

    const int r0 = row0 + warp * 16 + g;
#pragma unroll
    for (int at = 0; at < 8; at++) {
        int c = at * 8 + tg * 2;
        *(float2*)(outp + (size_t)r0 * H_DIM + c)       = make_float2(acc[at][0], acc[at][1]);
        *(float2*)(outp + (size_t)(r0 + 8) * H_DIM + c) = make_float2(acc[at][2], acc[at][3]);
    }
}

// ---------------------------------------------------------------------------
// Kernel 2: causal flash attention via tf32 mma.sync.
// Block 128 thr = 4 warps; BM=64 (16 rows/warp), BN=32 keys/tile.
// Each warp's P stays warp-local (only __syncwarp between S and PV).
// ---------------------------------------------------------------------------
__global__ __launch_bounds__(128) void flash_kernel(float* __restrict__ out)
{
    const int b  = blockIdx.y;
    const int qb = (T_SEQ / 64 - 1) - blockIdx.x;   // heavy blocks first
    const int row0 = qb * 64;

    const float* Qp = g_Q + (size_t)b * T_SEQ * H_DIM;
    const float* Kp = g_K + (size_t)b * T_SEQ * H_DIM;
    const float* Vp = g_V + (size_t)b * T_SEQ * H_DIM;

    __shared__ float Qs[64][68];   // [row][ch]   A-frag: 4g+tg conflict-free
    __shared__ float Ks[32][68];   // [key][ch]   B-frag: (n=key)*68 -> 4g+tg ok
    __shared__ float Vs[32][72];   // [key][h]    B-frag: (k=key)*72 -> 8tg+g ok
    __shared__ float Ps[64][36];   // [row][key]  A-frag: 4g+tg ok

    const int tid  = threadIdx.x;
    const int warp = tid >> 5;
    const int lane = tid & 31;
    const int g  = lane >> 2;
    const int tg = lane & 3;

    // Q tile 64x64 (tf32-rounded)
    for (int i = tid; i < 1024; i += 128) {
        int r = i >> 4, c4 = i & 15;
        float4 v = *(const float4*)(Qp + (size_t)(row0 + r) * H_DIM + c4 * 4);
        Qs[r][c4 * 4 + 0] = tfbits(v.x);
        Qs[r][c4 * 4 + 1] = tfbits(v.y);
        Qs[r][c4 * 4 + 2] = tfbits(v.z);
        Qs[r][c4 * 4 + 3] = tfbits(v.w);
    }

    float o[8][4];
#pragma unroll
    for (int a = 0; a < 8; a++)
#pragma unroll
        for (int j = 0; j < 4; j++) o[a][j] = 0.0f;
    float m0 = -1e30f, m1 = -1e30f, l0 = 0.0f, l1 = 0.0f;

    const int r0g = row0 + warp * 16 + g;   // this thread's even row
    const int r1g = r0g + 8;                // this thread's odd row
    const int nkb = 2 * qb + 2;

    for (int kb = 0; kb < nkb; kb++) {
        __syncthreads();
        // K tile 32x64, V tile 32x64 (tf32-rounded)
        for (int i = tid; i < 512; i += 128) {
            int r = i >> 4, c4 = i & 15;
            float4 kv = *(const float4*)(Kp + (size_t)(kb * 32 + r) * H_DIM + c4 * 4);
            Ks[r][c4 * 4 + 0] = tfbits(kv.x);
            Ks[r][c4 * 4 + 1] = tfbits(kv.y);
            Ks[r][c4 * 4 + 2] = tfbits(kv.z);
            Ks[r][c4 * 4 + 3] = tfbits(kv.w);
            float4 vv = *(const float4*)(Vp + (size_t)(kb * 32 + r) * H_DIM + c4 * 4);
            Vs[r][c4 * 4 + 0] = tfbits(vv.x);
            Vs[r][c4 * 4 + 1] = tfbits(vv.y);
            Vs[r][c4 * 4 + 2] = tfbits(vv.z);
            Vs[r][c4 * 4 + 3] = tfbits(vv.w);
        }
        __syncthreads();

        // ---- S = Q K^T : 4 atoms (32 keys), K-dim 64 in chunks of 8 ----
        float s[4][4];
#pragma unroll
        for (int a = 0; a < 4; a++)
#pragma unroll
            for (int j = 0; j < 4; j++) s[a][j] = 0.0f;

#pragma unroll
        for (int kc = 0; kc < 64; kc += 8) {
            unsigned a[4];
            a[0] = __float_as_uint(Qs[warp * 16 + g    ][kc + tg    ]);
            a[1] = __float_as_uint(Qs[warp * 16 + g + 8][kc + tg    ]);
            a[2] = __float_as_uint(Qs[warp * 16 + g    ][kc + tg + 4]);
            a[3] = __float_as_uint(Qs[warp * 16 + g + 8][kc + tg + 4]);
#pragma unroll
            for (int at = 0; at < 4; at++) {
                unsigned bfr[2];
                bfr[0] = __float_as_uint(Ks[at * 8 + g][kc + tg    ]);
                bfr[1] = __float_as_uint(Ks[at * 8 + g][kc + tg + 4]);
                mma_tf32(s[at], a, bfr);
            }
        }

        // ---- scale + causal mask ----
        const bool diag = (kb >= 2 * qb);
#pragma unroll
        for (int at = 0; at < 4; at++) {
            int c0 = kb * 32 + at * 8 + tg * 2;
            s[at][0] *= 0.125f; s[at][1] *= 0.125f;
            s[at][2] *= 0.125f; s[at][3] *= 0.125f;
            if (diag) {
                if (c0     > r0g) s[at][0] = -1e30f;
                if (c0 + 1 > r0g) s[at][1] = -1e30f;
                if (c0     > r1g) s[at][2] = -1e30f;
                if (c0 + 1 > r1g) s[at][3] = -1e30f;
            }
        }

        // ---- online softmax (rows split across 4 lanes of the quad) ----
        float tm0 = -1e30f, tm1 = -1e30f;
#pragma unroll
        for (int at = 0; at < 4; at++) {
            tm0 = fmaxf(tm0, fmaxf(s[at][0], s[at][1]));
            tm1 = fmaxf(tm1, fmaxf(s[at][2], s[at][3]));
        }
        tm0 = fmaxf(tm0, __shfl_xor_sync(0xffffffffu, tm0, 1));
        tm0 = fmaxf(tm0, __shfl_xor_sync(0xffffffffu, tm0, 2));
        tm1 = fmaxf(tm1, __shfl_xor_sync(0xffffffffu, tm1, 1));
        tm1 = fmaxf(tm1, __shfl_xor_sync(0xffffffffu, tm1, 2));

        float nm0 = fmaxf(m0, tm0), nm1 = fmaxf(m1, tm1);
        float al0 = __expf(m0 - nm0), al1 = __expf(m1 - nm1);
        m0 = nm0; m1 = nm1;

        float tl0 = 0.0f, tl1 = 0.0f;
#pragma unroll
        for (int at = 0; at < 4; at++) {
            s[at][0] = __expf(s[at][0] - nm0);
            s[at][1] = __expf(s[at][1] - nm0);
            s[at][2] = __expf(s[at][2] - nm1);
            s[at][3] = __expf(s[at][3] - nm1);
            tl0 += s[at][0] + s[at][1];
            tl1 += s[at][2] + s[at][3];
        }
        tl0 += __shfl_xor_sync(0xffffffffu, tl0, 1);
        tl0 += __shfl_xor_sync(0xffffffffu, tl0, 2);
        tl1 += __shfl_xor_sync(0xffffffffu, tl1, 1);
        tl1 += __shfl_xor_sync(0xffffffffu, tl1, 2);
        l0 = l0 * al0 + tl0;
        l1 = l1 * al1 + tl1;

        // rescale O accumulators
#pragma unroll
        for (int at = 0; at < 8; at++) {
            o[at][0] *= al0; o[at][1] *= al0;
            o[at][2] *= al1; o[at][3] *= al1;
        }

        // stage P (warp-local rows only)
#pragma unroll
        for (int at = 0; at < 4; at++) {
            int c = at * 8 + tg * 2;
            Ps[warp * 16 + g    ][c    ] = tfbits(s[at][0]);
            Ps[warp * 16 + g    ][c + 1] = tfbits(s[at][1]);
            Ps[warp * 16 + g + 8][c    ] = tfbits(s[at][2]);
            Ps[warp * 16 + g + 8][c + 1] = tfbits(s[at][3]);
        }
        __syncwarp();

        // ---- O += P V : 8 atoms (64 h), K-dim 32 in chunks of 8 ----
#pragma unroll
        for (int kc = 0; kc < 32; kc += 8) {
            unsigned a[4];
            a[0] = __float_as_uint(Ps[warp * 16 + g    ][kc + tg    ]);
            a[1] = __float_as_uint(Ps[warp * 16 + g + 8][kc + tg    ]);
            a[2] = __float_as_uint(Ps[warp * 16 + g    ][kc + tg + 4]);
            a[3] = __float_as_uint(Ps[warp * 16 + g + 8][kc + tg + 4]);
#pragma unroll
            for (int at = 0; at < 8; at++) {
                unsigned bfr[2];
                bfr[0] = __float_as_uint(Vs[kc + tg    ][at * 8 + g]);
                bfr[1] = __float_as_uint(Vs[kc + tg + 4][at * 8 + g]);
                mma_tf32(o[at], a, bfr);
            }
        }
        // next-iter top __syncthreads protects Ps/Ks/Vs reuse
    }

    // ---- write normalized output ----
    float inv0 = 1.0f / l0, inv1 = 1.0f / l1;
    float* ob = out + (size_t)b * T_SEQ * H_DIM;
#pragma unroll
    for (int at = 0; at < 8; at++) {
        int c = at * 8 + tg * 2;
        *(float2*)(ob + (size_t)r0g * H_DIM + c) =
            make_float2(o[at][0] * inv0, o[at][1] * inv0);
        *(float2*)(ob + (size_t)r1g * H_DIM + c) =
            make_float2(o[at][2] * inv1, o[at][3] * inv1);
    }
}

// ---------------------------------------------------------------------------
extern "C" void kernel_launch(void* const* d_in, const int* in_sizes, int n_in,
                              void* d_out, int out_size)
{
    const float* x  = (const float*)d_in[0];
    const float* Wq = (const float*)d_in[1];
    const float* Wk = (const float*)d_in[2];
    const float* Wv = (const float*)d_in[3];
    float* out = (float*)d_out;

    dim3 g1(NROWS / 128, 3);
    proj_kernel<<<g1, 256>>>(x, Wq, Wk, Wv);

    dim3 g2(T_SEQ / 64, B_BATCH);
    flash_kernel<<<g2, 128>>>(out);
}

// round 3
// speedup vs baseline: 3.1395x; 1.5261x over previous
#include <cuda_runtime.h>
#include <math.h>

#define T_SEQ   4096
#define B_BATCH 4
#define C_EMB   1024
#define H_DIM   64
#define NROWS   (B_BATCH * T_SEQ)   // 16384
#define QB_CNT  (T_SEQ / 64)        // 64 query blocks per batch
#define MAXCH   8                   // max 512-key chunks per q-block

__device__ float g_Q[NROWS * H_DIM];
__device__ float g_K[NROWS * H_DIM];
__device__ float g_V[NROWS * H_DIM];
// split-K partials: [b][qb][chunk][64 rows][64 cols] and [..][64 rows][m,l]
__device__ float g_Opart[(size_t)B_BATCH * QB_CNT * MAXCH * 64 * 64];
__device__ float g_ml[(size_t)B_BATCH * QB_CNT * MAXCH * 64 * 2];

// ---- helpers -------------------------------------------------------------
__device__ __forceinline__ unsigned f2tf(float f) {
    unsigned r;
    asm("cvt.rna.tf32.f32 %0, %1;" : "=r"(r) : "f"(f));
    return r;
}
__device__ __forceinline__ float tfbits(float f) {
    return __uint_as_float(f2tf(f));
}
__device__ __forceinline__ void mma_tf32(float* d, const unsigned* a, const unsigned* b) {
    asm("mma.sync.aligned.m16n8k8.row.col.f32.tf32.tf32.f32 "
        "{%0,%1,%2,%3}, {%4,%5,%6,%7}, {%8,%9}, {%0,%1,%2,%3};"
        : "+f"(d[0]), "+f"(d[1]), "+f"(d[2]), "+f"(d[3])
        : "r"(a[0]), "r"(a[1]), "r"(a[2]), "r"(a[3]), "r"(b[0]), "r"(b[1]));
}

// ---------------------------------------------------------------------------
// Kernel 1: QKV projection via tf32 mma.sync (unchanged from R2).
// ---------------------------------------------------------------------------
__global__ __launch_bounds__(256) void proj_kernel(
    const float* __restrict__ x,
    const float* __restrict__ Wq,
    const float* __restrict__ Wk,
    const float* __restrict__ Wv)
{
    const float* W;
    float* outp;
    if (blockIdx.y == 0)      { W = Wq; outp = g_Q; }
    else if (blockIdx.y == 1) { W = Wk; outp = g_K; }
    else                      { W = Wv; outp = g_V; }

    __shared__ float Xs[128][36];
    __shared__ float Ws[32][72];

    const int tid  = threadIdx.x;
    const int warp = tid >> 5;
    const int lane = tid & 31;
    const int g  = lane >> 2;
    const int tg = lane & 3;
    const int row0 = blockIdx.x * 128;

    float acc[8][4];
#pragma unroll
    for (int a = 0; a < 8; a++)
#pragma unroll
        for (int j = 0; j < 4; j++) acc[a][j] = 0.0f;

    for (int k0 = 0; k0 < C_EMB; k0 += 32) {
        for (int i = tid; i < 1024; i += 256) {
            int r = i >> 3, c4 = i & 7;
            float4 v = *(const float4*)(x + (size_t)(row0 + r) * C_EMB + k0 + c4 * 4);
            Xs[r][c4 * 4 + 0] = tfbits(v.x);
            Xs[r][c4 * 4 + 1] = tfbits(v.y);
            Xs[r][c4 * 4 + 2] = tfbits(v.z);
            Xs[r][c4 * 4 + 3] = tfbits(v.w);
        }
        for (int i = tid; i < 512; i += 256) {
            int r = i >> 4, c4 = i & 15;
            float4 v = *(const float4*)(W + (size_t)(k0 + r) * H_DIM + c4 * 4);
            Ws[r][c4 * 4 + 0] = tfbits(v.x);
            Ws[r][c4 * 4 + 1] = tfbits(v.y);
            Ws[r][c4 * 4 + 2] = tfbits(v.z);
            Ws[r][c4 * 4 + 3] = tfbits(v.w);
        }
        __syncthreads();

#pragma unroll
        for (int kc = 0; kc < 32; kc += 8) {
            unsigned a[4];
            a[0] = __float_as_uint(Xs[warp * 16 + g    ][kc + tg    ]);
            a[1] = __float_as_uint(Xs[warp * 16 + g + 8][kc + tg    ]);
            a[2] = __float_as_uint(Xs[warp * 16 + g    ][kc + tg + 4]);
            a[3] = __float_as_uint(Xs[warp * 16 + g + 8][kc + tg + 4]);
#pragma unroll
            for (int at = 0; at < 8; at++) {
                unsigned b[2];
                b[0] = __float_as_uint(Ws[kc + tg    ][at * 8 + g]);
                b[1] = __float_as_uint(Ws[kc + tg + 4][at * 8 + g]);
                mma_tf32(acc[at], a, b);
            }
        }
        __syncthreads();
    }

    const int r0 = row0 + warp * 16 + g;
#pragma unroll
    for (int at = 0; at < 8; at++) {
        int c = at * 8 + tg * 2;
        *(float2*)(outp + (size_t)r0 * H_DIM + c)       = make_float2(acc[at][0], acc[at][1]);
        *(float2*)(outp + (size_t)(r0 + 8) * H_DIM + c) = make_float2(acc[at][2], acc[at][3]);
    }
}

// ---------------------------------------------------------------------------
// Kernel 2: split-K flash partial.  CTA = (chunk, qb, b).
// Each chunk covers up to 512 keys = 16 tiles of 32.  Writes unnormalized
// partial O plus per-row (m, l) to scratch.
// ---------------------------------------------------------------------------
__global__ __launch_bounds__(128) void flash_part_kernel()
{
    const int chunk = blockIdx.x;
    const int qb    = blockIdx.y;
    const int b     = blockIdx.z;
    if (chunk * 8 > qb) return;            // chunk start beyond causal limit

    const int row0 = qb * 64;
    const int nkt  = min(16, (row0 + 64 - chunk * 512 + 31) / 32);

    const float* Qp = g_Q + (size_t)b * T_SEQ * H_DIM;
    const float* Kp = g_K + (size_t)b * T_SEQ * H_DIM;
    const float* Vp = g_V + (size_t)b * T_SEQ * H_DIM;

    __shared__ float Qs[64][68];
    __shared__ float Ks[32][68];
    __shared__ float Vs[32][72];
    __shared__ float Ps[64][36];

    const int tid  = threadIdx.x;
    const int warp = tid >> 5;
    const int lane = tid & 31;
    const int g  = lane >> 2;
    const int tg = lane & 3;

    for (int i = tid; i < 1024; i += 128) {
        int r = i >> 4, c4 = i & 15;
        float4 v = *(const float4*)(Qp + (size_t)(row0 + r) * H_DIM + c4 * 4);
        Qs[r][c4 * 4 + 0] = tfbits(v.x);
        Qs[r][c4 * 4 + 1] = tfbits(v.y);
        Qs[r][c4 * 4 + 2] = tfbits(v.z);
        Qs[r][c4 * 4 + 3] = tfbits(v.w);
    }

    float o[8][4];
#pragma unroll
    for (int a = 0; a < 8; a++)
#pragma unroll
        for (int j = 0; j < 4; j++) o[a][j] = 0.0f;
    float m0 = -1e30f, m1 = -1e30f, l0 = 0.0f, l1 = 0.0f;

    const int r0g = row0 + warp * 16 + g;
    const int r1g = r0g + 8;

    for (int kb = 0; kb < nkt; kb++) {
        const int key0 = (chunk * 16 + kb) * 32;
        __syncthreads();
        for (int i = tid; i < 512; i += 128) {
            int r = i >> 4, c4 = i & 15;
            float4 kv = *(const float4*)(Kp + (size_t)(key0 + r) * H_DIM + c4 * 4);
            Ks[r][c4 * 4 + 0] = tfbits(kv.x);
            Ks[r][c4 * 4 + 1] = tfbits(kv.y);
            Ks[r][c4 * 4 + 2] = tfbits(kv.z);
            Ks[r][c4 * 4 + 3] = tfbits(kv.w);
            float4 vv = *(const float4*)(Vp + (size_t)(key0 + r) * H_DIM + c4 * 4);
            Vs[r][c4 * 4 + 0] = tfbits(vv.x);
            Vs[r][c4 * 4 + 1] = tfbits(vv.y);
            Vs[r][c4 * 4 + 2] = tfbits(vv.z);
            Vs[r][c4 * 4 + 3] = tfbits(vv.w);
        }
        __syncthreads();

        // ---- S = Q K^T ----
        float s[4][4];
#pragma unroll
        for (int a = 0; a < 4; a++)
#pragma unroll
            for (int j = 0; j < 4; j++) s[a][j] = 0.0f;

#pragma unroll
        for (int kc = 0; kc < 64; kc += 8) {
            unsigned a[4];
            a[0] = __float_as_uint(Qs[warp * 16 + g    ][kc + tg    ]);
            a[1] = __float_as_uint(Qs[warp * 16 + g + 8][kc + tg    ]);
            a[2] = __float_as_uint(Qs[warp * 16 + g    ][kc + tg + 4]);
            a[3] = __float_as_uint(Qs[warp * 16 + g + 8][kc + tg + 4]);
#pragma unroll
            for (int at = 0; at < 4; at++) {
                unsigned bfr[2];
                bfr[0] = __float_as_uint(Ks[at * 8 + g][kc + tg    ]);
                bfr[1] = __float_as_uint(Ks[at * 8 + g][kc + tg + 4]);
                mma_tf32(s[at], a, bfr);
            }
        }

        // ---- scale + causal mask ----
        const bool diag = (key0 + 31 > row0);
#pragma unroll
        for (int at = 0; at < 4; at++) {
            int c0 = key0 + at * 8 + tg * 2;
            s[at][0] *= 0.125f; s[at][1] *= 0.125f;
            s[at][2] *= 0.125f; s[at][3] *= 0.125f;
            if (diag) {
                if (c0     > r0g) s[at][0] = -1e30f;
                if (c0 + 1 > r0g) s[at][1] = -1e30f;
                if (c0     > r1g) s[at][2] = -1e30f;
                if (c0 + 1 > r1g) s[at][3] = -1e30f;
            }
        }

        // ---- online softmax ----
        float tm0 = -1e30f, tm1 = -1e30f;
#pragma unroll
        for (int at = 0; at < 4; at++) {
            tm0 = fmaxf(tm0, fmaxf(s[at][0], s[at][1]));
            tm1 = fmaxf(tm1, fmaxf(s[at][2], s[at][3]));
        }
        tm0 = fmaxf(tm0, __shfl_xor_sync(0xffffffffu, tm0, 1));
        tm0 = fmaxf(tm0, __shfl_xor_sync(0xffffffffu, tm0, 2));
        tm1 = fmaxf(tm1, __shfl_xor_sync(0xffffffffu, tm1, 1));
        tm1 = fmaxf(tm1, __shfl_xor_sync(0xffffffffu, tm1, 2));

        float nm0 = fmaxf(m0, tm0), nm1 = fmaxf(m1, tm1);
        float al0 = __expf(m0 - nm0), al1 = __expf(m1 - nm1);
        m0 = nm0; m1 = nm1;

        float tl0 = 0.0f, tl1 = 0.0f;
#pragma unroll
        for (int at = 0; at < 4; at++) {
            s[at][0] = __expf(s[at][0] - nm0);
            s[at][1] = __expf(s[at][1] - nm0);
            s[at][2] = __expf(s[at][2] - nm1);
            s[at][3] = __expf(s[at][3] - nm1);
            tl0 += s[at][0] + s[at][1];
            tl1 += s[at][2] + s[at][3];
        }
        tl0 += __shfl_xor_sync(0xffffffffu, tl0, 1);
        tl0 += __shfl_xor_sync(0xffffffffu, tl0, 2);
        tl1 += __shfl_xor_sync(0xffffffffu, tl1, 1);
        tl1 += __shfl_xor_sync(0xffffffffu, tl1, 2);
        l0 = l0 * al0 + tl0;
        l1 = l1 * al1 + tl1;

#pragma unroll
        for (int at = 0; at < 8; at++) {
            o[at][0] *= al0; o[at][1] *= al0;
            o[at][2] *= al1; o[at][3] *= al1;
        }

#pragma unroll
        for (int at = 0; at < 4; at++) {
            int c = at * 8 + tg * 2;
            Ps[warp * 16 + g    ][c    ] = tfbits(s[at][0]);
            Ps[warp * 16 + g    ][c + 1] = tfbits(s[at][1]);
            Ps[warp * 16 + g + 8][c    ] = tfbits(s[at][2]);
            Ps[warp * 16 + g + 8][c + 1] = tfbits(s[at][3]);
        }
        __syncwarp();

        // ---- O += P V ----
#pragma unroll
        for (int kc = 0; kc < 32; kc += 8) {
            unsigned a[4];
            a[0] = __float_as_uint(Ps[warp * 16 + g    ][kc + tg    ]);
            a[1] = __float_as_uint(Ps[warp * 16 + g + 8][kc + tg    ]);
            a[2] = __float_as_uint(Ps[warp * 16 + g    ][kc + tg + 4]);
            a[3] = __float_as_uint(Ps[warp * 16 + g + 8][kc + tg + 4]);
#pragma unroll
            for (int at = 0; at < 8; at++) {
                unsigned bfr[2];
                bfr[0] = __float_as_uint(Vs[kc + tg    ][at * 8 + g]);
                bfr[1] = __float_as_uint(Vs[kc + tg + 4][at * 8 + g]);
                mma_tf32(o[at], a, bfr);
            }
        }
    }

    // ---- write partial (unnormalized O, m, l) ----
    const size_t pidx = ((size_t)(b * QB_CNT + qb) * MAXCH + chunk);
    float* Op = g_Opart + pidx * 64 * 64;
    float* mlp = g_ml + pidx * 64 * 2;

    const int lr0 = warp * 16 + g;     // local row (even)
#pragma unroll
    for (int at = 0; at < 8; at++) {
        int c = at * 8 + tg * 2;
        *(float2*)(Op + (size_t)lr0 * 64 + c)       = make_float2(o[at][0], o[at][1]);
        *(float2*)(Op + (size_t)(lr0 + 8) * 64 + c) = make_float2(o[at][2], o[at][3]);
    }
    if (tg == 0) {
        mlp[lr0 * 2 + 0] = m0;  mlp[lr0 * 2 + 1] = l0;
        mlp[(lr0 + 8) * 2 + 0] = m1;  mlp[(lr0 + 8) * 2 + 1] = l1;
    }
}

// ---------------------------------------------------------------------------
// Kernel 3: combine partials.  Block (64 rows, 4 col-segments of 16).
// ---------------------------------------------------------------------------
__global__ __launch_bounds__(256) void combine_kernel(float* __restrict__ out)
{
    const int qb = blockIdx.x;
    const int b  = blockIdx.y;
    const int row = threadIdx.x;       // 0..63
    const int cs  = threadIdx.y;       // 0..3
    const int nc  = qb / 8 + 1;

    const size_t base = (size_t)(b * QB_CNT + qb) * MAXCH;

    float mv[MAXCH], lv[MAXCH];
    float M = -1e30f;
    for (int c = 0; c < nc; c++) {
        mv[c] = g_ml[(base + c) * 128 + row * 2 + 0];
        lv[c] = g_ml[(base + c) * 128 + row * 2 + 1];
        M = fmaxf(M, mv[c]);
    }

    float L = 0.0f;
    float acc[16];
#pragma unroll
    for (int j = 0; j < 16; j++) acc[j] = 0.0f;

    for (int c = 0; c < nc; c++) {
        float w = __expf(mv[c] - M);
        L += w * lv[c];
        const float* Op = g_Opart + (base + c) * 4096 + (size_t)row * 64 + cs * 16;
#pragma unroll
        for (int j4 = 0; j4 < 4; j4++) {
            float4 v = *(const float4*)(Op + j4 * 4);
            acc[j4 * 4 + 0] += w * v.x;
            acc[j4 * 4 + 1] += w * v.y;
            acc[j4 * 4 + 2] += w * v.z;
            acc[j4 * 4 + 3] += w * v.w;
        }
    }

    float inv = 1.0f / L;
    float* op = out + (size_t)b * T_SEQ * H_DIM + (size_t)(qb * 64 + row) * H_DIM + cs * 16;
#pragma unroll
    for (int j4 = 0; j4 < 4; j4++)
        *(float4*)(op + j4 * 4) = make_float4(acc[j4 * 4 + 0] * inv, acc[j4 * 4 + 1] * inv,
                                              acc[j4 * 4 + 2] * inv, acc[j4 * 4 + 3] * inv);
}

// ---------------------------------------------------------------------------
extern "C" void kernel_launch(void* const* d_in, const int* in_sizes, int n_in,
                              void* d_out, int out_size)
{
    const float* x  = (const float*)d_in[0];
    const float* Wq = (const float*)d_in[1];
    const float* Wk = (const float*)d_in[2];
    const float* Wv = (const float*)d_in[3];
    float* out = (float*)d_out;

    dim3 g1(NROWS / 128, 3);
    proj_kernel<<<g1, 256>>>(x, Wq, Wk, Wv);

    dim3 g2(MAXCH, QB_CNT, B_BATCH);
    flash_part_kernel<<<g2, 128>>>();

    dim3 g3(QB_CNT, B_BATCH);
    combine_kernel<<<g3, dim3(64, 4)>>>(out);
}

// round 7
// speedup vs baseline: 3.9871x; 1.2700x over previous
#include <cuda_runtime.h>
#include <math.h>

#define T_SEQ   4096
#define B_BATCH 4
#define C_EMB   1024
#define H_DIM   64
#define NROWS   (B_BATCH * T_SEQ)   // 16384
#define QB_CNT  (T_SEQ / 64)        // 64 query blocks per batch
#define MAXCH   16                  // 256-key chunks per q-block
#define KSPLIT  4                   // proj k-splits (256 k each)

__device__ float g_Q[NROWS * H_DIM];
__device__ float g_K[NROWS * H_DIM];
__device__ float g_V[NROWS * H_DIM];
// split-K partials: [b][qb][chunk][64 rows][64 cols] and [..][64 rows][m,l]
__device__ float g_Opart[(size_t)B_BATCH * QB_CNT * MAXCH * 64 * 64];
__device__ float g_ml[(size_t)B_BATCH * QB_CNT * MAXCH * 64 * 2];

// ---- helpers -------------------------------------------------------------
__device__ __forceinline__ unsigned f2tf(float f) {
    unsigned r;
    asm("cvt.rna.tf32.f32 %0, %1;" : "=r"(r) : "f"(f));
    return r;
}
__device__ __forceinline__ float tfbits(float f) {
    return __uint_as_float(f2tf(f));
}
__device__ __forceinline__ void mma_tf32(float* d, const unsigned* a, const unsigned* b) {
    asm("mma.sync.aligned.m16n8k8.row.col.f32.tf32.tf32.f32 "
        "{%0,%1,%2,%3}, {%4,%5,%6,%7}, {%8,%9}, {%0,%1,%2,%3};"
        : "+f"(d[0]), "+f"(d[1]), "+f"(d[2]), "+f"(d[3])
        : "r"(a[0]), "r"(a[1]), "r"(a[2]), "r"(a[3]), "r"(b[0]), "r"(b[1]));
}

// ---------------------------------------------------------------------------
// Kernel 0: zero Q/K/V accumulators (proj uses atomicAdd).
// 1024 blocks x 256 thr, one float4 per array per thread.
// ---------------------------------------------------------------------------
__global__ __launch_bounds__(256) void zero_qkv()
{
    size_t i = (size_t)blockIdx.x * blockDim.x + threadIdx.x;
    float4 z = make_float4(0.f, 0.f, 0.f, 0.f);
    ((float4*)g_Q)[i] = z;
    ((float4*)g_K)[i] = z;
    ((float4*)g_V)[i] = z;
}

// ---------------------------------------------------------------------------
// Kernel 1: QKV projection, split-K.
// Block = (rowtile 128, ksplit of 256, output sel).  256 thr = 8 warps,
// warp w -> rows w*16..+15, 8 n-atoms.  Register-prefetch next chunk.
// ---------------------------------------------------------------------------
__global__ __launch_bounds__(256) void proj_kernel(
    const float* __restrict__ x,
    const float* __restrict__ Wq,
    const float* __restrict__ Wk,
    const float* __restrict__ Wv)
{
    const float* W;
    float* outp;
    if (blockIdx.z == 0)      { W = Wq; outp = g_Q; }
    else if (blockIdx.z == 1) { W = Wk; outp = g_K; }
    else                      { W = Wv; outp = g_V; }

    __shared__ float Xs[128][36];
    __shared__ float Ws[32][72];

    const int tid  = threadIdx.x;
    const int warp = tid >> 5;
    const int lane = tid & 31;
    const int g  = lane >> 2;
    const int tg = lane & 3;
    const int row0  = blockIdx.x * 128;
    const int kbase = blockIdx.y * (C_EMB / KSPLIT);

    float acc[8][4];
#pragma unroll
    for (int a = 0; a < 8; a++)
#pragma unroll
        for (int j = 0; j < 4; j++) acc[a][j] = 0.0f;

    float4 px[4], pw[2];
    // prefetch chunk 0
#pragma unroll
    for (int s = 0; s < 4; s++) {
        int idx = tid + s * 256, r = idx >> 3, c4 = idx & 7;
        px[s] = *(const float4*)(x + (size_t)(row0 + r) * C_EMB + kbase + c4 * 4);
    }
#pragma unroll
    for (int s = 0; s < 2; s++) {
        int idx = tid + s * 256, r = idx >> 4, c4 = idx & 15;
        pw[s] = *(const float4*)(W + (size_t)(kbase + r) * H_DIM + c4 * 4);
    }

    for (int c = 0; c < C_EMB / KSPLIT / 32; c++) {
        // store prefetched chunk (tf32-rounded)
#pragma unroll
        for (int s = 0; s < 4; s++) {
            int idx = tid + s * 256, r = idx >> 3, c4 = idx & 7;
            Xs[r][c4 * 4 + 0] = tfbits(px[s].x);
            Xs[r][c4 * 4 + 1] = tfbits(px[s].y);
            Xs[r][c4 * 4 + 2] = tfbits(px[s].z);
            Xs[r][c4 * 4 + 3] = tfbits(px[s].w);
        }
#pragma unroll
        for (int s = 0; s < 2; s++) {
            int idx = tid + s * 256, r = idx >> 4, c4 = idx & 15;
            Ws[r][c4 * 4 + 0] = tfbits(pw[s].x);
            Ws[r][c4 * 4 + 1] = tfbits(pw[s].y);
            Ws[r][c4 * 4 + 2] = tfbits(pw[s].z);
            Ws[r][c4 * 4 + 3] = tfbits(pw[s].w);
        }
        __syncthreads();

        // prefetch next chunk while MMAs run
        if (c + 1 < C_EMB / KSPLIT / 32) {
            int k0 = kbase + (c + 1) * 32;
#pragma unroll
            for (int s = 0; s < 4; s++) {
                int idx = tid + s * 256, r = idx >> 3, c4 = idx & 7;
                px[s] = *(const float4*)(x + (size_t)(row0 + r) * C_EMB + k0 + c4 * 4);
            }
#pragma unroll
            for (int s = 0; s < 2; s++) {
                int idx = tid + s * 256, r = idx >> 4, c4 = idx & 15;
                pw[s] = *(const float4*)(W + (size_t)(k0 + r) * H_DIM + c4 * 4);
            }
        }

#pragma unroll
        for (int kc = 0; kc < 32; kc += 8) {
            unsigned a[4];
            a[0] = __float_as_uint(Xs[warp * 16 + g    ][kc + tg    ]);
            a[1] = __float_as_uint(Xs[warp * 16 + g + 8][kc + tg    ]);
            a[2] = __float_as_uint(Xs[warp * 16 + g    ][kc + tg + 4]);
            a[3] = __float_as_uint(Xs[warp * 16 + g + 8][kc + tg + 4]);
#pragma unroll
            for (int at = 0; at < 8; at++) {
                unsigned b[2];
                b[0] = __float_as_uint(Ws[kc + tg    ][at * 8 + g]);
                b[1] = __float_as_uint(Ws[kc + tg + 4][at * 8 + g]);
                mma_tf32(acc[at], a, b);
            }
        }
        __syncthreads();
    }

    // accumulate partial into global (zeroed beforehand)
    const int r0 = row0 + warp * 16 + g;
#pragma unroll
    for (int at = 0; at < 8; at++) {
        int cc = at * 8 + tg * 2;
        atomicAdd(&outp[(size_t)r0 * H_DIM + cc],           acc[at][0]);
        atomicAdd(&outp[(size_t)r0 * H_DIM + cc + 1],       acc[at][1]);
        atomicAdd(&outp[(size_t)(r0 + 8) * H_DIM + cc],     acc[at][2]);
        atomicAdd(&outp[(size_t)(r0 + 8) * H_DIM + cc + 1], acc[at][3]);
    }
}

// ---------------------------------------------------------------------------
// Kernel 2: split-K flash partial.  CTA = (chunk of 256 keys, qb, b).
// Heavy q-blocks launch first.  Register double-buffer for K/V tiles.
// ---------------------------------------------------------------------------
__global__ __launch_bounds__(128) void flash_part_kernel()
{
    const int chunk = blockIdx.x;
    const int qb    = (QB_CNT - 1) - blockIdx.y;   // heavy blocks first
    const int b     = blockIdx.z;
    if (chunk * 4 > qb) return;                    // beyond causal limit

    const int row0 = qb * 64;
    const int nkt  = min(8, (row0 + 64 - chunk * 256 + 31) / 32);

    const float* Qp = g_Q + (size_t)b * T_SEQ * H_DIM;
    const float* Kp = g_K + (size_t)b * T_SEQ * H_DIM;
    const float* Vp = g_V + (size_t)b * T_SEQ * H_DIM;

    __shared__ float Qs[64][68];
    __shared__ float Ks[32][68];
    __shared__ float Vs[32][72];
    __shared__ float Ps[64][36];

    const int tid  = threadIdx.x;
    const int warp = tid >> 5;
    const int lane = tid & 31;
    const int g  = lane >> 2;
    const int tg = lane & 3;

    for (int i = tid; i < 1024; i += 128) {
        int r = i >> 4, c4 = i & 15;
        float4 v = *(const float4*)(Qp + (size_t)(row0 + r) * H_DIM + c4 * 4);
        Qs[r][c4 * 4 + 0] = tfbits(v.x);
        Qs[r][c4 * 4 + 1] = tfbits(v.y);
        Qs[r][c4 * 4 + 2] = tfbits(v.z);
        Qs[r][c4 * 4 + 3] = tfbits(v.w);
    }

    float o[8][4];
#pragma unroll
    for (int a = 0; a < 8; a++)
#pragma unroll
        for (int j = 0; j < 4; j++) o[a][j] = 0.0f;
    float m0 = -1e30f, m1 = -1e30f, l0 = 0.0f, l1 = 0.0f;

    const int r0g = row0 + warp * 16 + g;
    const int r1g = r0g + 8;

    float4 pk[4], pv[4];
    // prefetch tile 0
    {
        const int key0 = chunk * 256;
#pragma unroll
        for (int s = 0; s < 4; s++) {
            int idx = tid + s * 128, r = idx >> 4, c4 = idx & 15;
            pk[s] = *(const float4*)(Kp + (size_t)(key0 + r) * H_DIM + c4 * 4);
            pv[s] = *(const float4*)(Vp + (size_t)(key0 + r) * H_DIM + c4 * 4);
        }
    }

    for (int kb = 0; kb < nkt; kb++) {
        const int key0 = chunk * 256 + kb * 32;
        __syncthreads();
        // store prefetched K/V (tf32-rounded)
#pragma unroll
        for (int s = 0; s < 4; s++) {
            int idx = tid + s * 128, r = idx >> 4, c4 = idx & 15;
            Ks[r][c4 * 4 + 0] = tfbits(pk[s].x);
            Ks[r][c4 * 4 + 1] = tfbits(pk[s].y);
            Ks[r][c4 * 4 + 2] = tfbits(pk[s].z);
            Ks[r][c4 * 4 + 3] = tfbits(pk[s].w);
            Vs[r][c4 * 4 + 0] = tfbits(pv[s].x);
            Vs[r][c4 * 4 + 1] = tfbits(pv[s].y);
            Vs[r][c4 * 4 + 2] = tfbits(pv[s].z);
            Vs[r][c4 * 4 + 3] = tfbits(pv[s].w);
        }
        __syncthreads();

        // prefetch next tile while computing
        if (kb + 1 < nkt) {
            const int keyn = chunk * 256 + (kb + 1) * 32;
#pragma unroll
            for (int s = 0; s < 4; s++) {
                int idx = tid + s * 128, r = idx >> 4, c4 = idx & 15;
                pk[s] = *(const float4*)(Kp + (size_t)(keyn + r) * H_DIM + c4 * 4);
                pv[s] = *(const float4*)(Vp + (size_t)(keyn + r) * H_DIM + c4 * 4);
            }
        }

        // ---- S = Q K^T ----
        float s[4][4];
#pragma unroll
        for (int a = 0; a < 4; a++)
#pragma unroll
            for (int j = 0; j < 4; j++) s[a][j] = 0.0f;

#pragma unroll
        for (int kc = 0; kc < 64; kc += 8) {
            unsigned a[4];
            a[0] = __float_as_uint(Qs[warp * 16 + g    ][kc + tg    ]);
            a[1] = __float_as_uint(Qs[warp * 16 + g + 8][kc + tg    ]);
            a[2] = __float_as_uint(Qs[warp * 16 + g    ][kc + tg + 4]);
            a[3] = __float_as_uint(Qs[warp * 16 + g + 8][kc + tg + 4]);
#pragma unroll
            for (int at = 0; at < 4; at++) {
                unsigned bfr[2];
                bfr[0] = __float_as_uint(Ks[at * 8 + g][kc + tg    ]);
                bfr[1] = __float_as_uint(Ks[at * 8 + g][kc + tg + 4]);
                mma_tf32(s[at], a, bfr);
            }
        }

        // ---- scale + causal mask ----
        const bool diag = (key0 + 31 > row0);
#pragma unroll
        for (int at = 0; at < 4; at++) {
            int c0 = key0 + at * 8 + tg * 2;
            s[at][0] *= 0.125f; s[at][1] *= 0.125f;
            s[at][2] *= 0.125f; s[at][3] *= 0.125f;
            if (diag) {
                if (c0     > r0g) s[at][0] = -1e30f;
                if (c0 + 1 > r0g) s[at][1] = -1e30f;
                if (c0     > r1g) s[at][2] = -1e30f;
                if (c0 + 1 > r1g) s[at][3] = -1e30f;
            }
        }

        // ---- online softmax ----
        float tm0 = -1e30f, tm1 = -1e30f;
#pragma unroll
        for (int at = 0; at < 4; at++) {
            tm0 = fmaxf(tm0, fmaxf(s[at][0], s[at][1]));
            tm1 = fmaxf(tm1, fmaxf(s[at][2], s[at][3]));
        }
        tm0 = fmaxf(tm0, __shfl_xor_sync(0xffffffffu, tm0, 1));
        tm0 = fmaxf(tm0, __shfl_xor_sync(0xffffffffu, tm0, 2));
        tm1 = fmaxf(tm1, __shfl_xor_sync(0xffffffffu, tm1, 1));
        tm1 = fmaxf(tm1, __shfl_xor_sync(0xffffffffu, tm1, 2));

        float nm0 = fmaxf(m0, tm0), nm1 = fmaxf(m1, tm1);
        float al0 = __expf(m0 - nm0), al1 = __expf(m1 - nm1);
        m0 = nm0; m1 = nm1;

        float tl0 = 0.0f, tl1 = 0.0f;
#pragma unroll
        for (int at = 0; at < 4; at++) {
            s[at][0] = __expf(s[at][0] - nm0);
            s[at][1] = __expf(s[at][1] - nm0);
            s[at][2] = __expf(s[at][2] - nm1);
            s[at][3] = __expf(s[at][3] - nm1);
            tl0 += s[at][0] + s[at][1];
            tl1 += s[at][2] + s[at][3];
        }
        tl0 += __shfl_xor_sync(0xffffffffu, tl0, 1);
        tl0 += __shfl_xor_sync(0xffffffffu, tl0, 2);
        tl1 += __shfl_xor_sync(0xffffffffu, tl1, 1);
        tl1 += __shfl_xor_sync(0xffffffffu, tl1, 2);
        l0 = l0 * al0 + tl0;
        l1 = l1 * al1 + tl1;

#pragma unroll
        for (int at = 0; at < 8; at++) {
            o[at][0] *= al0; o[at][1] *= al0;
            o[at][2] *= al1; o[at][3] *= al1;
        }

#pragma unroll
        for (int at = 0; at < 4; at++) {
            int c = at * 8 + tg * 2;
            Ps[warp * 16 + g    ][c    ] = tfbits(s[at][0]);
            Ps[warp * 16 + g    ][c + 1] = tfbits(s[at][1]);
            Ps[warp * 16 + g + 8][c    ] = tfbits(s[at][2]);
            Ps[warp * 16 + g + 8][c + 1] = tfbits(s[at][3]);
        }
        __syncwarp();

        // ---- O += P V ----
#pragma unroll
        for (int kc = 0; kc < 32; kc += 8) {
            unsigned a[4];
            a[0] = __float_as_uint(Ps[warp * 16 + g    ][kc + tg    ]);
            a[1] = __float_as_uint(Ps[warp * 16 + g + 8][kc + tg    ]);
            a[2] = __float_as_uint(Ps[warp * 16 + g    ][kc + tg + 4]);
            a[3] = __float_as_uint(Ps[warp * 16 + g + 8][kc + tg + 4]);
#pragma unroll
            for (int at = 0; at < 8; at++) {
                unsigned bfr[2];
                bfr[0] = __float_as_uint(Vs[kc + tg    ][at * 8 + g]);
                bfr[1] = __float_as_uint(Vs[kc + tg + 4][at * 8 + g]);
                mma_tf32(o[at], a, bfr);
            }
        }
    }

    // ---- write partial (unnormalized O, m, l) ----
    const size_t pidx = ((size_t)(b * QB_CNT + qb) * MAXCH + chunk);
    float* Op = g_Opart + pidx * 64 * 64;
    float* mlp = g_ml + pidx * 64 * 2;

    const int lr0 = warp * 16 + g;
#pragma unroll
    for (int at = 0; at < 8; at++) {
        int c = at * 8 + tg * 2;
        *(float2*)(Op + (size_t)lr0 * 64 + c)       = make_float2(o[at][0], o[at][1]);
        *(float2*)(Op + (size_t)(lr0 + 8) * 64 + c) = make_float2(o[at][2], o[at][3]);
    }
    if (tg == 0) {
        mlp[lr0 * 2 + 0] = m0;  mlp[lr0 * 2 + 1] = l0;
        mlp[(lr0 + 8) * 2 + 0] = m1;  mlp[(lr0 + 8) * 2 + 1] = l1;
    }
}

// ---------------------------------------------------------------------------
// Kernel 3: combine partials.
// ---------------------------------------------------------------------------
__global__ __launch_bounds__(256) void combine_kernel(float* __restrict__ out)
{
    const int qb = blockIdx.x;
    const int b  = blockIdx.y;
    const int row = threadIdx.x;       // 0..63
    const int cs  = threadIdx.y;       // 0..3
    const int nc  = qb / 4 + 1;

    const size_t base = (size_t)(b * QB_CNT + qb) * MAXCH;

    float mv[MAXCH], lv[MAXCH];
    float M = -1e30f;
    for (int c = 0; c < nc; c++) {
        mv[c] = g_ml[(base + c) * 128 + row * 2 + 0];
        lv[c] = g_ml[(base + c) * 128 + row * 2 + 1];
        M = fmaxf(M, mv[c]);
    }

    float L = 0.0f;
    float acc[16];
#pragma unroll
    for (int j = 0; j < 16; j++) acc[j] = 0.0f;

    for (int c = 0; c < nc; c++) {
        float w = __expf(mv[c] - M);
        L += w * lv[c];
        const float* Op = g_Opart + (base + c) * 4096 + (size_t)row * 64 + cs * 16;
#pragma unroll
        for (int j4 = 0; j4 < 4; j4++) {
            float4 v = *(const float4*)(Op + j4 * 4);
            acc[j4 * 4 + 0] += w * v.x;
            acc[j4 * 4 + 1] += w * v.y;
            acc[j4 * 4 + 2] += w * v.z;
            acc[j4 * 4 + 3] += w * v.w;
        }
    }

    float inv = 1.0f / L;
    float* op = out + (size_t)b * T_SEQ * H_DIM + (size_t)(qb * 64 + row) * H_DIM + cs * 16;
#pragma unroll
    for (int j4 = 0; j4 < 4; j4++)
        *(float4*)(op + j4 * 4) = make_float4(acc[j4 * 4 + 0] * inv, acc[j4 * 4 + 1] * inv,
                                              acc[j4 * 4 + 2] * inv, acc[j4 * 4 + 3] * inv);
}

// ---------------------------------------------------------------------------
extern "C" void kernel_launch(void* const* d_in, const int* in_sizes, int n_in,
                              void* d_out, int out_size)
{
    const float* x  = (const float*)d_in[0];
    const float* Wq = (const float*)d_in[1];
    const float* Wk = (const float*)d_in[2];
    const float* Wv = (const float*)d_in[3];
    float* out = (float*)d_out;

    zero_qkv<<<NROWS * H_DIM / 4 / 256, 256>>>();

    dim3 g1(NROWS / 128, KSPLIT, 3);
    proj_kernel<<<g1, 256>>>(x, Wq, Wk, Wv);

    dim3 g2(MAXCH, QB_CNT, B_BATCH);
    flash_part_kernel<<<g2, 128>>>();

    dim3 g3(QB_CNT, B_BATCH);
    combine_kernel<<<g3, dim3(64, 4)>>>(out);
}